// round 11
// baseline (speedup 1.0000x reference)
#include <cuda_runtime.h>
#include <cuda_bf16.h>
#include <cstdint>
#include <cstddef>

#define B_ 4
#define V_ 64
#define E_ 1024
#define L_ 1024
#define D_ 256
#define BE_ (B_*E_)
#define SLOTS 16
#define MAXE 16

// ---------------- device scratch ----------------
// Fragment-ordered Mt images (identical layout to R9):
// uint4 index: (jt*16 + s)*32 + lane,  jt = j16-tile 0..15, s = d-slice 0..15
__device__ __align__(16) unsigned char g_BfH[16*16*32*16];   // 128KB
__device__ __align__(16) unsigned char g_BfL[16*16*32*16];   // 128KB
__device__ __align__(16) float g_u[D_];
__device__ __align__(16) float g_t[D_];
__device__ float g_c;
__device__ int   g_ndeg[V_];
__device__ int   g_ecnt[V_];
__device__ int   g_ndst[V_*SLOTS];
__device__ int   g_vedge[V_*MAXE];   // e | (slot<<16)
__device__ int   g_eslot[E_];
__device__ float g_adjw[B_*V_*SLOTS];

// ---------------- helpers ----------------
__device__ __forceinline__ uint32_t smem_u32(const void* p) {
    uint32_t a;
    asm("{ .reg .u64 t; cvta.to.shared.u64 t, %1; cvt.u32.u64 %0, t; }" : "=r"(a) : "l"(p));
    return a;
}
__device__ __forceinline__ void ldsm4(uint32_t* r, uint32_t addr) {
    asm volatile("ldmatrix.sync.aligned.m8n8.x4.shared.b16 {%0,%1,%2,%3}, [%4];"
        : "=r"(r[0]), "=r"(r[1]), "=r"(r[2]), "=r"(r[3]) : "r"(addr));
}
__device__ __forceinline__ void mma16816(float* d, const uint32_t* a, uint32_t b0, uint32_t b1) {
    asm volatile("mma.sync.aligned.m16n8k16.row.col.f32.bf16.bf16.f32 "
        "{%0,%1,%2,%3}, {%4,%5,%6,%7}, {%8,%9}, {%0,%1,%2,%3};"
        : "+f"(d[0]), "+f"(d[1]), "+f"(d[2]), "+f"(d[3])
        : "r"(a[0]), "r"(a[1]), "r"(a[2]), "r"(a[3]), "r"(b0), "r"(b1));
}
__device__ __forceinline__ uint32_t pack_bf2(float a, float b) {
    __nv_bfloat162 t = __floats2bfloat162_rn(a, b);
    return *reinterpret_cast<uint32_t*>(&t);
}
// split fp32 pair -> (hi bf16x2, lo bf16x2)
__device__ __forceinline__ void split2(float a, float b, uint32_t& hi, uint32_t& lo) {
    __nv_bfloat16 ha = __float2bfloat16(a), hb = __float2bfloat16(b);
    __nv_bfloat162 hp = make_bfloat162(ha, hb);
    hi = *(uint32_t*)&hp;
    lo = pack_bf2(a - __bfloat162float(ha), b - __bfloat162float(hb));
}

// A row stride: 264 bf16 = 528B
#define ASTR 528
// partial-S region: [16][68] fp32 per warp
#define PSTR 68
#define PREG (16*PSTR)          // floats per region

// smem byte offsets
#define SM_AHI  0               // 33792
#define SM_ALO  33792           // 33792
#define SM_PART 67584           // 16 regions x 4352B = 69632
#define MS_DST  137216
#define MS_ADJ  141312
#define MS_VED  145408
#define MS_DEG  149504
#define MS_ECNT 149760
#define MS_P    150016
#define MS_R    150272
#define MS_PP   150528
#define MS_RP   152576
#define MS_MX   154624
#define MS_INV  154880
#define SMEM_BYTES 155136

// ---------------- K0: fragment images + u, t, c (layout identical to R9) ----------------
__global__ void k0_prep(const float* __restrict__ Wq, const float* __restrict__ bq,
                        const float* __restrict__ Wk, const float* __restrict__ bk) {
    __shared__ float swk[D_];
    const int j = blockIdx.x, d = threadIdx.x;
    swk[d] = Wk[d*D_ + j];
    __syncthreads();
    float acc = 0.f;
#pragma unroll 8
    for (int k = 0; k < D_; ++k) acc += Wq[k*D_ + d] * swk[k];
    {   // B[k=d][n=j] = M[d][j]; scatter into mma B-fragment order
        __nv_bfloat16 hi = __float2bfloat16(acc);
        __nv_bfloat16 lo = __float2bfloat16(acc - __bfloat162float(hi));
        const int s = d >> 4, dk = d & 15;
        const int r = dk >> 3, k2 = (dk >> 1) & 3, half = dk & 1;
        const int jt = j >> 4, n8l = (j >> 3) & 1;
        const int lane = (j & 7)*4 + k2;
        const int w = n8l*2 + r;
        const uint32_t word = (((uint32_t)jt*16 + s)*32 + lane)*4 + w;
        const uint32_t byte = word*4 + half*2;
        *reinterpret_cast<__nv_bfloat16*>(g_BfH + byte) = hi;
        *reinterpret_cast<__nv_bfloat16*>(g_BfL + byte) = lo;
    }
    if (d == 0) {
        float s = 0.f;
        for (int k = 0; k < D_; ++k) s += bq[k] * swk[k];
        g_t[j] = s;
    }
    if (j == 0) {
        float s = 0.f;
        for (int k = 0; k < D_; ++k) s += Wq[k*D_ + d] * bk[k];
        g_u[d] = s;
    }
    if (j == 0 && d == 0) {
        float s = 0.f;
        for (int k = 0; k < D_; ++k) s += bq[k] * bk[k];
        g_c = s;
    }
}

// ---------------- K1 / K1b: graph metadata ----------------
__global__ void k1_build(const int* __restrict__ ei) {
    const int v = threadIdx.x;
    int deg = 0, ecnt = 0;
    for (int e = 0; e < E_; ++e) {
        int s = ei[e];
        if (s == v) {
            int dd = ei[BE_ + e];
            int slot = -1;
            for (int k = 0; k < deg; ++k)
                if (g_ndst[v*SLOTS + k] == dd) { slot = k; break; }
            if (slot < 0 && deg < SLOTS) { slot = deg; g_ndst[v*SLOTS + deg] = dd; ++deg; }
            if (slot >= 0) {
                g_eslot[e] = slot;
                if (ecnt < MAXE) g_vedge[v*MAXE + ecnt++] = e | (slot << 16);
            }
        }
    }
    g_ndeg[v] = deg;
    g_ecnt[v] = ecnt;
    for (int b = 0; b < B_; ++b)
        for (int k = 0; k < SLOTS; ++k)
            g_adjw[(b*V_ + v)*SLOTS + k] = 0.f;
}

__global__ void k1b_adjw(const int* __restrict__ ei, const float* __restrict__ ew) {
    const int i = blockIdx.x * blockDim.x + threadIdx.x;
    if (i >= BE_) return;
    const int e = i & (E_ - 1);
    const int b = i >> 10;
    const int v = ei[i];
    const int slot = g_eslot[e];
    atomicAdd(&g_adjw[(b*V_ + v)*SLOTS + slot], ew[i]);
}

// ---------------- K2: fused per-(b,l) attention; T lives in registers ----------------
__global__ void __launch_bounds__(512, 1) k2_main(
    const float* __restrict__ hs, const float* __restrict__ attn_skip,
    float* __restrict__ ew_out) {
    extern __shared__ __align__(16) unsigned char sm[];
    const uint32_t sb = smem_u32(sm);
    const int tid = threadIdx.x;
    const int lane = tid & 31, warp = tid >> 5;
    const int b = blockIdx.x >> 10;
    const int l = blockIdx.x & 1023;

    int*   sDst  = (int*)(sm + MS_DST);
    float* sAdj  = (float*)(sm + MS_ADJ);
    int*   sVed  = (int*)(sm + MS_VED);
    int*   sDeg  = (int*)(sm + MS_DEG);
    int*   sEcnt = (int*)(sm + MS_ECNT);
    float* sP    = (float*)(sm + MS_P);
    float* sR    = (float*)(sm + MS_R);
    float* sPp   = (float*)(sm + MS_PP);
    float* sRp   = (float*)(sm + MS_RP);
    float* sMx   = (float*)(sm + MS_MX);
    float* sInv  = (float*)(sm + MS_INV);
    float* sPart = (float*)(sm + SM_PART);

    // metadata
    if (tid < 64) { sDeg[tid] = g_ndeg[tid]; sEcnt[tid] = g_ecnt[tid]; }
    for (int i = tid; i < 64*SLOTS; i += 512) {
        sDst[i] = g_ndst[i];
        sAdj[i] = g_adjw[b*64*SLOTS + i];
    }
    for (int i = tid; i < 64*MAXE; i += 512) sVed[i] = g_vedge[i];

    // H load + bf16 split + bias partials
    {
        const int v = tid >> 3, part = tid & 7;
        const float4* hrow = (const float4*)(hs
            + (((size_t)(b*64 + v))*1024 + l)*256) + part*8;
        const float4* u4 = (const float4*)g_u + part*8;
        const float4* t4 = (const float4*)g_t + part*8;
        float pp = 0.f, rr = 0.f;
#pragma unroll
        for (int i = 0; i < 8; ++i) {
            float4 f = hrow[i];
            float4 uu = u4[i], tt = t4[i];
            pp += f.x*uu.x + f.y*uu.y + f.z*uu.z + f.w*uu.w;
            rr += f.x*tt.x + f.y*tt.y + f.z*tt.z + f.w*tt.w;
            uint32_t hi01, lo01, hi23, lo23;
            split2(f.x, f.y, hi01, lo01);
            split2(f.z, f.w, hi23, lo23);
            const uint32_t off = (uint32_t)v*ASTR + (uint32_t)(part*32 + i*4)*2;
            *(uint2*)(sm + SM_AHI + off) = make_uint2(hi01, hi23);
            *(uint2*)(sm + SM_ALO + off) = make_uint2(lo01, lo23);
        }
        sPp[tid] = pp; sRp[tid] = rr;
    }
    __syncthreads();

    // bias reduction
    if (tid < 64) {
        float p = 0.f, r = 0.f;
#pragma unroll
        for (int i = 0; i < 8; ++i) { p += sPp[tid*8 + i]; r += sRp[tid*8 + i]; }
        sP[tid] = p; sR[tid] = r;
    }

    // ---- GEMM1: warp (mr, kc) computes T rows mr*16..+16, cols kc*64..+64 ----
    const int mr = warp >> 2;          // 0..3
    const int kc = warp & 3;           // 0..3
    const int arow = lane & 15;
    const int akoff = (lane >> 4) * 8;
    const int bjoff = ((lane >> 4) << 3) + (lane & 7);
    const int bdk = ((lane >> 3) & 1) * 8;

    const uint4* BH = (const uint4*)g_BfH;
    const uint4* BL = (const uint4*)g_BfL;
    // uint4 idx for (jj, s): ((4*kc + jj)*16 + s)*32 + lane
    const int bbase = (4*kc*16)*32 + lane;   // + jj*16*32 + s*32

    float acc[8][4];
#pragma unroll
    for (int n8 = 0; n8 < 8; ++n8)
#pragma unroll
        for (int i = 0; i < 4; ++i) acc[n8][i] = 0.f;

    uint4 cH[4], cL[4];
#pragma unroll
    for (int jj = 0; jj < 4; ++jj) {
        cH[jj] = BH[bbase + jj*512];
        cL[jj] = BL[bbase + jj*512];
    }

    for (int s = 0; s < 16; ++s) {
        uint4 nH[4], nL[4];
        if (s < 15) {
#pragma unroll
            for (int jj = 0; jj < 4; ++jj) {
                nH[jj] = BH[bbase + jj*512 + (s+1)*32];
                nL[jj] = BL[bbase + jj*512 + (s+1)*32];
            }
        }
        uint32_t aHi[4], aLo[4];
        const uint32_t ao = (uint32_t)(mr*16 + arow)*ASTR + (uint32_t)(s*16 + akoff)*2;
        ldsm4(aHi, sb + SM_AHI + ao);
        ldsm4(aLo, sb + SM_ALO + ao);
#pragma unroll
        for (int jj = 0; jj < 4; ++jj) {
            mma16816(acc[jj*2+0], aHi, cH[jj].x, cH[jj].y);
            mma16816(acc[jj*2+0], aHi, cL[jj].x, cL[jj].y);
            mma16816(acc[jj*2+0], aLo, cH[jj].x, cH[jj].y);
            mma16816(acc[jj*2+1], aHi, cH[jj].z, cH[jj].w);
            mma16816(acc[jj*2+1], aHi, cL[jj].z, cL[jj].w);
            mma16816(acc[jj*2+1], aLo, cH[jj].z, cH[jj].w);
        }
        if (s < 15) {
#pragma unroll
            for (int jj = 0; jj < 4; ++jj) { cH[jj] = nH[jj]; cL[jj] = nL[jj]; }
        }
    }

    // ---- GEMM2: S partial (rows mr*16..+16, all 64 n) over k = kc*64..+64 ----
    // A-fragments come straight from acc (C-frag of two adjacent n8 tiles == A-frag of k16).
    float acc2[8][4];
#pragma unroll
    for (int n8 = 0; n8 < 8; ++n8)
#pragma unroll
        for (int i = 0; i < 4; ++i) acc2[n8][i] = 0.f;

#pragma unroll
    for (int q = 0; q < 4; ++q) {
        uint32_t aH2[4], aL2[4];
        split2(acc[2*q][0],   acc[2*q][1],   aH2[0], aL2[0]);
        split2(acc[2*q][2],   acc[2*q][3],   aH2[1], aL2[1]);
        split2(acc[2*q+1][0], acc[2*q+1][1], aH2[2], aL2[2]);
        split2(acc[2*q+1][2], acc[2*q+1][3], aH2[3], aL2[3]);
        const int s2 = kc*4 + q;
#pragma unroll
        for (int nt = 0; nt < 4; ++nt) {
            uint32_t bHi[4], bLo[4];
            const uint32_t bo = (uint32_t)(nt*16 + bjoff)*ASTR + (uint32_t)(s2*16 + bdk)*2;
            ldsm4(bHi, sb + SM_AHI + bo);
            ldsm4(bLo, sb + SM_ALO + bo);
#pragma unroll
            for (int h = 0; h < 2; ++h) {
                mma16816(acc2[nt*2+h], aH2, bHi[2*h], bHi[2*h+1]);
                mma16816(acc2[nt*2+h], aH2, bLo[2*h], bLo[2*h+1]);
                mma16816(acc2[nt*2+h], aL2, bHi[2*h], bHi[2*h+1]);
            }
        }
    }

    // ---- store k-partials to per-warp scratch ----
    {
        float* reg = sPart + warp*PREG;
        const int g = lane >> 2, t2 = lane & 3;
#pragma unroll
        for (int n8 = 0; n8 < 8; ++n8) {
            const int col = n8*8 + t2*2;
            *(float2*)&reg[g*PSTR + col]       = make_float2(acc2[n8][0], acc2[n8][1]);
            *(float2*)&reg[(g+8)*PSTR + col]   = make_float2(acc2[n8][2], acc2[n8][3]);
        }
    }
    __syncthreads();

    // ---- softmax step 1: per-v max & inv-sum (sum 4 k-partials on the fly) ----
    if (tid < 64) {
        const int v = tid, deg = sDeg[v];
        const float pv = sP[v], cC = g_c;
        const float* base = sPart + ((v >> 4)*4)*PREG + (v & 15)*PSTR;
        float mx = -1e30f;
        float sc[SLOTS];
        for (int k = 0; k < deg; ++k) {
            const int w = sDst[v*SLOTS + k];
            const float raw = base[w] + base[PREG + w] + base[2*PREG + w] + base[3*PREG + w];
            const float s = (raw + pv + sR[w] + cC) * 0.0625f;
            sc[k] = s;
            mx = fmaxf(mx, s);
        }
        float sum = 0.f;
        for (int k = 0; k < deg; ++k) sum += __expf(sc[k] - mx);
        sMx[v] = mx;
        sInv[v] = 1.f / sum;
    }
    __syncthreads();

    // ---- step 2: parallel per-edge output ----
    {
        const int v = tid >> 3;
        const int j0 = (tid & 7) * 2;
        const int ecnt = sEcnt[v];
        const float pv = sP[v], cC = g_c;
        const float mx = sMx[v], inv = sInv[v];
        const float ask = *attn_skip, osk = 1.f - ask;
        const float* base = sPart + ((v >> 4)*4)*PREG + (v & 15)*PSTR;
#pragma unroll
        for (int jj = 0; jj < 2; ++jj) {
            const int j = j0 + jj;
            if (j < ecnt) {
                const int w = sVed[v*MAXE + j];
                const int e = w & 0xFFFF, slot = w >> 16;
                const int dd = sDst[v*SLOTS + slot];
                const float raw = base[dd] + base[PREG + dd] + base[2*PREG + dd] + base[3*PREG + dd];
                const float s = (raw + pv + sR[dd] + cC) * 0.0625f;
                const float gval = ask * sAdj[v*SLOTS + slot] + osk * (__expf(s - mx) * inv);
                ew_out[((size_t)(b*E_ + e))*L_ + l] = gval;
            }
        }
    }
}

// ---------------- K3: ei broadcast output ----------------
__global__ void k3_ei(const int* __restrict__ ei, float* __restrict__ out) {
    const size_t i = (size_t)blockIdx.x * blockDim.x + threadIdx.x;
    const size_t n = (size_t)2 * BE_ * L_;
    if (i < n) out[i] = (float)ei[i >> 10];
}

// ---------------- launch ----------------
extern "C" void kernel_launch(void* const* d_in, const int* in_sizes, int n_in,
                              void* d_out, int out_size) {
    const float* hs  = (const float*)d_in[0];
    const int*   ei  = (const int*)d_in[1];
    const float* ew  = (const float*)d_in[2];
    const float* Wq  = (const float*)d_in[3];
    const float* bq  = (const float*)d_in[4];
    const float* Wk  = (const float*)d_in[5];
    const float* bk  = (const float*)d_in[6];
    const float* ask = (const float*)d_in[7];

    float* out = (float*)d_out;
    const int EW_ELEMS = BE_ * L_;
    const int EI_ELEMS = 2 * BE_ * L_;
    float* ew_out = out;
    bool write_ei = false;
    if (out_size >= EI_ELEMS + EW_ELEMS) {
        write_ei = true;
        ew_out = out + EI_ELEMS;
    }

    cudaFuncSetAttribute(k2_main, cudaFuncAttributeMaxDynamicSharedMemorySize, SMEM_BYTES);

    k0_prep<<<D_, D_>>>(Wq, bq, Wk, bk);
    k1_build<<<1, V_>>>(ei);
    k1b_adjw<<<(BE_ + 255)/256, 256>>>(ei, ew);
    k2_main<<<B_*L_, 512, SMEM_BYTES>>>(hs, ask, ew_out);
    if (write_ei) k3_ei<<<(EI_ELEMS + 255)/256, 256>>>(ei, out);
}